// round 15
// baseline (speedup 1.0000x reference)
#include <cuda_runtime.h>
#include <cuda_fp16.h>
#include <cstdint>

// ---------------- Problem constants ----------------
#define BATCH   16
#define CIN     32
#define WH_IN   224
#define WH_OUT  222
#define COUT    64
#define TILES_PER_CTA 48                 // 148 CTAs * 48 = 7104 = 16*222*2
#define OPLANE  (BATCH * WH_OUT * WH_OUT)
#define NTHREADS 320

// ---------------- SMEM layout ----------------
// A: ring of 6 row slots. Slot = 136 px * 16 words (32 ch as fp16x2, pos-permuted,
// XOR-swizzled by px&3). px-stride 64B. One LDS.128 per (px, quad q) feeds both
// ks of one tap (a0/a2 for chalf 0 and 1); +512B gives px+8 (a1/a3).
#define SLOT_BYTES 8704                  // 136 * 64
#define NSLOTS     6
#define A_BYTES    (NSLOTS * SLOT_BYTES) // 52224
#define SM_B       A_BYTES
// B[n][q 0..3][tap 0..8][4 words]: q-stride 144B, tap-stride 16B, n-stride 704B
// (176 words == 16 mod 32 -> LDS.128 phases conflict-free).
#define BSTR_N     704
#define SMEM_BYTES (SM_B + COUT * BSTR_N)  // 97280

// Barrier ids: full[it&3] = 1..4 (128 = producers 64 + team 64),
//              empty[it&3] = 5..8 (128)
#define BAR_SYNC(id, n)   asm volatile("bar.sync %0, %1;"   :: "r"(id), "r"(n) : "memory")
#define BAR_ARRIVE(id, n) asm volatile("bar.arrive %0, %1;" :: "r"(id), "r"(n) : "memory")
#define MEMBAR_CTA()      asm volatile("membar.cta;" ::: "memory")

// ---------------- helpers ----------------
static __device__ __forceinline__ uint32_t smem_u32(const void* p) {
    uint32_t a;
    asm("{ .reg .u64 t; cvta.to.shared.u64 t, %1; cvt.u32.u64 %0, t; }" : "=r"(a) : "l"(p));
    return a;
}
static __device__ __forceinline__ void lds_u128(uint32_t a, uint32_t* v) {
    asm volatile("ld.shared.v4.b32 {%0,%1,%2,%3}, [%4];"
                 : "=r"(v[0]), "=r"(v[1]), "=r"(v[2]), "=r"(v[3]) : "r"(a));
}
static __device__ __forceinline__ void sts_u128(uint32_t a, const uint32_t* v) {
    asm volatile("st.shared.v4.b32 [%0], {%1,%2,%3,%4};"
                 :: "r"(a), "r"(v[0]), "r"(v[1]), "r"(v[2]), "r"(v[3]));
}
// pack two f32 -> f16x2 word: LOW half = v0, HIGH half = v1
static __device__ __forceinline__ uint32_t pack_f16x2(float v0, float v1) {
    uint32_t w;
    asm("cvt.rn.f16x2.f32 %0, %1, %2;" : "=r"(w) : "f"(v1), "f"(v0));
    return w;
}
static __device__ __forceinline__ void mma_f16(float* d,
                                               uint32_t a0, uint32_t a1, uint32_t a2, uint32_t a3,
                                               uint32_t b0, uint32_t b1) {
    asm volatile(
        "mma.sync.aligned.m16n8k16.row.col.f32.f16.f16.f32 "
        "{%0,%1,%2,%3}, {%4,%5,%6,%7}, {%8,%9}, {%0,%1,%2,%3};"
        : "+f"(d[0]), "+f"(d[1]), "+f"(d[2]), "+f"(d[3])
        : "r"(a0), "r"(a1), "r"(a2), "r"(a3), "r"(b0), "r"(b1));
}

// Stage one input row yr into its ring slot (2 producer warps, ptid 0..63).
// Unit u = (p4 = u>>2, Q = u&3): loads 8 channel rows (4 px each) covering the
// channel-pairs of logical quad Q, packs, stores 4 swizzled STS.128.
static __device__ __forceinline__ void stage_row(const float* __restrict__ x,
                                                 int b, int xs, int yr,
                                                 uint32_t a_sm, int ptid) {
    const uint32_t slot = a_sm + (uint32_t)((yr % NSLOTS) * SLOT_BYTES);
    #pragma unroll 1
    for (int u = ptid; u < 136; u += 64) {
        const int p4 = u >> 2;
        const int Q  = u & 3;
        float4 va[4], vb[4];
        #pragma unroll
        for (int inner = 0; inner < 4; ++inner) {
            const int cp = ((inner >> 1) * 8) + Q + 4 * (inner & 1);
            const int c0 = 2 * cp;
            const float* g0 = x + ((size_t)(b * CIN + c0) * WH_IN + yr) * WH_IN + xs + p4 * 4;
            va[inner] = *(const float4*)g0;
            vb[inner] = *(const float4*)(g0 + WH_IN * WH_IN);
        }
        #pragma unroll
        for (int i = 0; i < 4; ++i) {
            uint32_t wd[4];
            wd[0] = pack_f16x2(((const float*)&va[0])[i], ((const float*)&vb[0])[i]);
            wd[1] = pack_f16x2(((const float*)&va[1])[i], ((const float*)&vb[1])[i]);
            wd[2] = pack_f16x2(((const float*)&va[2])[i], ((const float*)&vb[2])[i]);
            wd[3] = pack_f16x2(((const float*)&va[3])[i], ((const float*)&vb[3])[i]);
            sts_u128(slot + (uint32_t)((p4 * 4 + i) * 64 + ((Q ^ i) << 4)), wd);
        }
    }
}

__global__ void __launch_bounds__(NTHREADS, 1)
quanv_v128_kernel(const float* __restrict__ x, const float* __restrict__ w,
                  float* __restrict__ out)
{
    extern __shared__ char smem[];
    const uint32_t a_sm = smem_u32(smem);
    const uint32_t b_sm = a_sm + SM_B;

    const int tid = threadIdx.x;
    const int wid = tid >> 5;
    const int lid = tid & 31;
    const int t0  = blockIdx.x * TILES_PER_CTA;

    // ---- one-time: build B[n][q][tap][inner] ----
    // inner: chalf = inner>>1, i0 = inner&1; c = chalf*16 + 2*(q + 4*i0)
    #pragma unroll 1
    for (int u = tid; u < COUT * 36; u += NTHREADS) {
        const int n   = u / 36;
        const int rem = u - n * 36;
        const int q   = rem / 9;
        const int tap = rem - q * 9;
        uint32_t bw[4];
        #pragma unroll
        for (int inner = 0; inner < 4; ++inner) {
            const int c = ((inner >> 1) * 16) + 2 * (q + 4 * (inner & 1));
            bw[inner] = pack_f16x2(w[n * 288 + c * 9 + tap],
                                   w[n * 288 + (c + 1) * 9 + tap]);
        }
        sts_u128(b_sm + (uint32_t)(n * BSTR_N + q * 144 + tap * 16), bw);
    }
    __syncthreads();

    if (wid < 8) {
        // ==== CONSUMERS: 4 teams x 2 warps; warp = M64 x N64 ====
        const int team = wid >> 1;        // tiles it ≡ team (mod 4)
        const int wx   = wid & 1;         // M64 half of the M128 tile
        const int r = lid >> 2, q = lid & 3;
        const uint32_t bB = b_sm + (uint32_t)(r * BSTR_N + q * 144);

        #pragma unroll 1
        for (int it = team; it < TILES_PER_CTA; it += 4) {
            const int t    = t0 + it;
            const int g    = t / WH_OUT;
            const int y    = t - g * WH_OUT;
            const int b    = g >> 1;
            const int half = g & 1;
            const int x0   = half ? 94 : 0;
            const int xoff = half ? 6 : 0;

            BAR_SYNC(1 + (it & 3), 128);            // rows staged for tile it

            uint32_t so[3];
            #pragma unroll
            for (int d = 0; d < 3; ++d)
                so[d] = (uint32_t)(((y + d) % NSLOTS) * SLOT_BYTES);

            // per-dx swizzled pixel bases (include a_sm)
            const int pxr = xoff + wx * 64 + r;
            uint32_t pb[3];
            #pragma unroll
            for (int dx = 0; dx < 3; ++dx) {
                const int P = pxr + dx;
                pb[dx] = a_sm + (uint32_t)(P * 64 + ((q ^ (P & 3)) << 4));
            }

            float acc[4][8][4];
            #pragma unroll
            for (int j = 0; j < 4; ++j)
                #pragma unroll
                for (int nb = 0; nb < 8; ++nb)
                    #pragma unroll
                    for (int e = 0; e < 4; ++e) acc[j][nb][e] = 0.0f;

            #pragma unroll
            for (int tap = 0; tap < 9; ++tap) {
                const int dy = tap / 3, dx = tap % 3;
                const uint32_t base = pb[dx] + so[dy];
                uint32_t lo[4][4], hi[4][4];
                #pragma unroll
                for (int j = 0; j < 4; ++j) {
                    lds_u128(base + (uint32_t)(j * 1024), lo[j]);        // px rows r
                    lds_u128(base + (uint32_t)(j * 1024 + 512), hi[j]);  // px rows r+8
                }
                #pragma unroll
                for (int nb = 0; nb < 8; ++nb) {
                    uint32_t bq[4];
                    lds_u128(bB + (uint32_t)(nb * 8 * BSTR_N + tap * 16), bq);
                    #pragma unroll
                    for (int j = 0; j < 4; ++j) {
                        // ks even (chalf 0)
                        mma_f16(acc[j][nb], lo[j][0], hi[j][0], lo[j][1], hi[j][1],
                                bq[0], bq[1]);
                        // ks odd (chalf 1)
                        mma_f16(acc[j][nb], lo[j][2], hi[j][2], lo[j][3], hi[j][3],
                                bq[2], bq[3]);
                    }
                }
            }

            BAR_ARRIVE(5 + (it & 3), 128);          // smem reads done (ring class)

            float* ob = out + ((size_t)b * WH_OUT + y) * WH_OUT + x0 + wx * 64
                            + (size_t)(2 * q) * OPLANE;
            #pragma unroll
            for (int j = 0; j < 4; ++j) {
                const int px = j * 16 + r;
                #pragma unroll
                for (int nb = 0; nb < 8; ++nb) {
                    float* p = ob + (size_t)(nb * 8) * OPLANE;
                    p[px]              = acc[j][nb][0];
                    p[OPLANE + px]     = acc[j][nb][1];
                    p[px + 8]          = acc[j][nb][2];
                    p[OPLANE + px + 8] = acc[j][nb][3];
                }
            }
        }
    } else {
        // ==== PRODUCERS: 2 warps, rolling 1-row stage, unified drain ====
        const int ptid = tid - 256;       // 0..63
        int synced = -1;
        #pragma unroll 1
        for (int it = 0; it < TILES_PER_CTA; ++it) {
            const int t    = t0 + it;
            const int g    = t / WH_OUT;
            const int y    = t - g * WH_OUT;
            const int b    = g >> 1;
            const int xs   = (g & 1) ? 88 : 0;

            const int target = (it == 0) ? -1 : ((y == 0) ? it - 1 : it - 4);
            for (int k = synced + 1; k <= target; ++k)
                BAR_SYNC(5 + (k & 3), 128);
            if (target > synced) synced = target;

            if (it == 0 || y == 0) {
                stage_row(x, b, xs, y + 0, a_sm, ptid);
                stage_row(x, b, xs, y + 1, a_sm, ptid);
                stage_row(x, b, xs, y + 2, a_sm, ptid);
            } else {
                stage_row(x, b, xs, y + 2, a_sm, ptid);
            }
            MEMBAR_CTA();
            BAR_ARRIVE(1 + (it & 3), 128);          // rows staged for tile it
        }
    }
}

extern "C" void kernel_launch(void* const* d_in, const int* in_sizes, int n_in,
                              void* d_out, int out_size)
{
    const float* x = (const float*)d_in[0];
    const float* w = (const float*)d_in[1];
    float* out = (float*)d_out;

    static bool attr_set = false;
    if (!attr_set) {
        cudaFuncSetAttribute(quanv_v128_kernel,
                             cudaFuncAttributeMaxDynamicSharedMemorySize, SMEM_BYTES);
        attr_set = true;
    }
    quanv_v128_kernel<<<148, NTHREADS, SMEM_BYTES>>>(x, w, out);
}

// round 16
// speedup vs baseline: 1.5703x; 1.5703x over previous
#include <cuda_runtime.h>
#include <cuda_fp16.h>
#include <cstdint>

// ---------------- Problem constants ----------------
#define BATCH   16
#define CIN     32
#define WH_IN   224
#define WH_OUT  222
#define COUT    64
#define TILES_PER_CTA 48                 // 148 CTAs * 48 = 7104 = 16*222*2
#define OPLANE  (BATCH * WH_OUT * WH_OUT)
#define NTHREADS 384

// ---------------- SMEM layout ----------------
// A: ring of 6 row slots, v128 layout. Slot = 136 px * 64B (16 words: 32 ch as
// fp16x2, quad-permuted, XOR-swizzled by px&3). One LDS.128 at granule
// (q^(P&3)) of pixel P = words {cp=q, q+4 | 8+q, 12+q}; +512B -> pixel P+8.
#define SLOT_BYTES 8704                  // 136 * 64
#define NSLOTS     6
#define A_BYTES    (NSLOTS * SLOT_BYTES) // 52224
#define SM_B       A_BYTES
// B[n][q 0..3][tap 0..8][4 words]: q-stride 144B, tap-stride 16B, n-stride 704B
// (176 words == 16 mod 32 -> LDS.128 phases conflict-free).
#define BSTR_N     704
#define SMEM_BYTES (SM_B + COUT * BSTR_N)  // 97280

// Barrier ids: full[it&3] = 1..4 (256 = producers 128 + team 128),
//              empty[it&3] = 5..8 (256), rendezvous = 9 (384)
#define BAR_SYNC(id, n)   asm volatile("bar.sync %0, %1;"   :: "r"(id), "r"(n) : "memory")
#define BAR_ARRIVE(id, n) asm volatile("bar.arrive %0, %1;" :: "r"(id), "r"(n) : "memory")
#define MEMBAR_CTA()      asm volatile("membar.cta;" ::: "memory")

// ---------------- helpers ----------------
static __device__ __forceinline__ uint32_t smem_u32(const void* p) {
    uint32_t a;
    asm("{ .reg .u64 t; cvta.to.shared.u64 t, %1; cvt.u32.u64 %0, t; }" : "=r"(a) : "l"(p));
    return a;
}
static __device__ __forceinline__ void lds_u128(uint32_t a, uint32_t* v) {
    asm volatile("ld.shared.v4.b32 {%0,%1,%2,%3}, [%4];"
                 : "=r"(v[0]), "=r"(v[1]), "=r"(v[2]), "=r"(v[3]) : "r"(a));
}
static __device__ __forceinline__ void sts_u128(uint32_t a, const uint32_t* v) {
    asm volatile("st.shared.v4.b32 [%0], {%1,%2,%3,%4};"
                 :: "r"(a), "r"(v[0]), "r"(v[1]), "r"(v[2]), "r"(v[3]));
}
// pack two f32 -> f16x2 word: LOW half = v0, HIGH half = v1
static __device__ __forceinline__ uint32_t pack_f16x2(float v0, float v1) {
    uint32_t w;
    asm("cvt.rn.f16x2.f32 %0, %1, %2;" : "=r"(w) : "f"(v1), "f"(v0));
    return w;
}
static __device__ __forceinline__ void mma_f16(float* d,
                                               uint32_t a0, uint32_t a1, uint32_t a2, uint32_t a3,
                                               uint32_t b0, uint32_t b1) {
    asm volatile(
        "mma.sync.aligned.m16n8k16.row.col.f32.f16.f16.f32 "
        "{%0,%1,%2,%3}, {%4,%5,%6,%7}, {%8,%9}, {%0,%1,%2,%3};"
        : "+f"(d[0]), "+f"(d[1]), "+f"(d[2]), "+f"(d[3])
        : "r"(a0), "r"(a1), "r"(a2), "r"(a3), "r"(b0), "r"(b1));
}

// Stage one input row yr into its ring slot (4 producer warps, ptid 0..127).
// Unit u = (p4 = u>>2, Q = u&3): loads 8 channel rows (4 px each) of logical
// quad Q, packs fp16x2, stores 4 swizzled STS.128.
static __device__ __forceinline__ void stage_row(const float* __restrict__ x,
                                                 int b, int xs, int yr,
                                                 uint32_t a_sm, int ptid) {
    const uint32_t slot = a_sm + (uint32_t)((yr % NSLOTS) * SLOT_BYTES);
    #pragma unroll 1
    for (int u = ptid; u < 136; u += 128) {
        const int p4 = u >> 2;
        const int Q  = u & 3;
        float4 va[4], vb[4];
        #pragma unroll
        for (int inner = 0; inner < 4; ++inner) {
            const int cp = ((inner >> 1) * 8) + Q + 4 * (inner & 1);
            const float* g0 = x + ((size_t)(b * CIN + 2 * cp) * WH_IN + yr) * WH_IN
                                + xs + p4 * 4;
            va[inner] = *(const float4*)g0;
            vb[inner] = *(const float4*)(g0 + WH_IN * WH_IN);
        }
        #pragma unroll
        for (int i = 0; i < 4; ++i) {
            uint32_t wd[4];
            wd[0] = pack_f16x2(((const float*)&va[0])[i], ((const float*)&vb[0])[i]);
            wd[1] = pack_f16x2(((const float*)&va[1])[i], ((const float*)&vb[1])[i]);
            wd[2] = pack_f16x2(((const float*)&va[2])[i], ((const float*)&vb[2])[i]);
            wd[3] = pack_f16x2(((const float*)&va[3])[i], ((const float*)&vb[3])[i]);
            sts_u128(slot + (uint32_t)((p4 * 4 + i) * 64 + ((Q ^ i) << 4)), wd);
        }
    }
}

__global__ void __launch_bounds__(NTHREADS, 1)
quanv_v2k_kernel(const float* __restrict__ x, const float* __restrict__ w,
                 float* __restrict__ out)
{
    extern __shared__ char smem[];
    const uint32_t a_sm = smem_u32(smem);
    const uint32_t b_sm = a_sm + SM_B;

    const int tid = threadIdx.x;
    const int wid = tid >> 5;
    const int lid = tid & 31;
    const int t0  = blockIdx.x * TILES_PER_CTA;

    // ---- one-time: build B[n][q][tap][inner] ----
    // inner: chalf = inner>>1, i0 = inner&1; c = chalf*16 + 2*(q + 4*i0)
    #pragma unroll 1
    for (int u = tid; u < COUT * 36; u += NTHREADS) {
        const int n   = u / 36;
        const int rem = u - n * 36;
        const int q   = rem / 9;
        const int tap = rem - q * 9;
        uint32_t bw[4];
        #pragma unroll
        for (int inner = 0; inner < 4; ++inner) {
            const int c = ((inner >> 1) * 16) + 2 * (q + 4 * (inner & 1));
            bw[inner] = pack_f16x2(w[n * 288 + c * 9 + tap],
                                   w[n * 288 + (c + 1) * 9 + tap]);
        }
        sts_u128(b_sm + (uint32_t)(n * BSTR_N + q * 144 + tap * 16), bw);
    }
    __syncthreads();

    if (wid < 8) {
        // ==== CONSUMERS: 2 teams x 4 warps; warp = M32 x N64 ====
        const int team = wid >> 2;        // warps 0-3 team0, 4-7 team1
        const int wx   = wid & 3;         // M-quarter (32 px)
        const int r = lid >> 2, q = lid & 3;
        const uint32_t bB = b_sm + (uint32_t)(r * BSTR_N + q * 144);

        #pragma unroll 1
        for (int it = team; it < TILES_PER_CTA; it += 2) {
            const int t    = t0 + it;
            const int g    = t / WH_OUT;
            const int y    = t - g * WH_OUT;
            const int b    = g >> 1;
            const int half = g & 1;
            const int x0   = half ? 94 : 0;
            const int xoff = half ? 6 : 0;

            if ((y == 0 && it > 0) || (y == 1 && it > 1))
                BAR_SYNC(9, 384);                   // boundary rendezvous
            BAR_SYNC(1 + (it & 3), 256);            // rows staged for tile it

            uint32_t so[3];
            #pragma unroll
            for (int d = 0; d < 3; ++d)
                so[d] = (uint32_t)(((y + d) % NSLOTS) * SLOT_BYTES);

            // per-dx swizzled pixel bases (j=0; j=1 is +16*64B)
            const int pxr = xoff + wx * 32 + r;
            uint32_t pb[3];
            #pragma unroll
            for (int dx = 0; dx < 3; ++dx) {
                const int P = pxr + dx;
                pb[dx] = a_sm + (uint32_t)(P * 64 + ((q ^ (P & 3)) << 4));
            }

            float acc[2][8][4];
            #pragma unroll
            for (int j = 0; j < 2; ++j)
                #pragma unroll
                for (int nb = 0; nb < 8; ++nb)
                    #pragma unroll
                    for (int e = 0; e < 4; ++e) acc[j][nb][e] = 0.0f;

            #pragma unroll
            for (int tap = 0; tap < 9; ++tap) {
                const int dy = tap / 3, dx = tap % 3;
                const uint32_t base = pb[dx] + so[dy];
                uint32_t lo[2][4], hi[2][4];
                #pragma unroll
                for (int j = 0; j < 2; ++j) {
                    lds_u128(base + (uint32_t)(j * 1024), lo[j]);        // px row r
                    lds_u128(base + (uint32_t)(j * 1024 + 512), hi[j]);  // px row r+8
                }
                #pragma unroll
                for (int nb = 0; nb < 8; ++nb) {
                    uint32_t bq[4];
                    lds_u128(bB + (uint32_t)(nb * 8 * BSTR_N + tap * 16), bq);
                    #pragma unroll
                    for (int j = 0; j < 2; ++j) {
                        mma_f16(acc[j][nb], lo[j][0], hi[j][0], lo[j][1], hi[j][1],
                                bq[0], bq[1]);      // ks even (ch 0..15)
                        mma_f16(acc[j][nb], lo[j][2], hi[j][2], lo[j][3], hi[j][3],
                                bq[2], bq[3]);      // ks odd  (ch 16..31)
                    }
                }
            }

            BAR_ARRIVE(5 + (it & 3), 256);          // smem reads done (ring class)

            float* ob = out + ((size_t)b * WH_OUT + y) * WH_OUT + x0 + wx * 32
                            + (size_t)(2 * q) * OPLANE;
            #pragma unroll
            for (int j = 0; j < 2; ++j) {
                const int px = j * 16 + r;
                #pragma unroll
                for (int nb = 0; nb < 8; ++nb) {
                    float* p = ob + (size_t)(nb * 8) * OPLANE;
                    p[px]              = acc[j][nb][0];
                    p[OPLANE + px]     = acc[j][nb][1];
                    p[px + 8]          = acc[j][nb][2];
                    p[OPLANE + px + 8] = acc[j][nb][3];
                }
            }
        }
    } else {
        // ==== PRODUCERS: 4 warps, rolling 1-row stage, unified drain ====
        const int ptid = tid - 256;       // 0..127
        int synced = -1;
        #pragma unroll 1
        for (int it = 0; it < TILES_PER_CTA; ++it) {
            const int t  = t0 + it;
            const int g  = t / WH_OUT;
            const int y  = t - g * WH_OUT;
            const int b  = g >> 1;
            const int xs = (g & 1) ? 88 : 0;

            if (y == 0 && it > 0) BAR_SYNC(9, 384); // boundary rendezvous
            const int target = (it == 0) ? -1 : ((y == 0) ? it - 1 : it - 4);
            for (int k = synced + 1; k <= target; ++k)
                BAR_SYNC(5 + (k & 3), 256);
            if (target > synced) synced = target;

            if (it == 0 || y == 0) {
                stage_row(x, b, xs, y + 0, a_sm, ptid);
                stage_row(x, b, xs, y + 1, a_sm, ptid);
                stage_row(x, b, xs, y + 2, a_sm, ptid);
            } else {
                stage_row(x, b, xs, y + 2, a_sm, ptid);
            }
            MEMBAR_CTA();
            BAR_ARRIVE(1 + (it & 3), 256);          // rows staged for tile it
        }
    }
}

extern "C" void kernel_launch(void* const* d_in, const int* in_sizes, int n_in,
                              void* d_out, int out_size)
{
    const float* x = (const float*)d_in[0];
    const float* w = (const float*)d_in[1];
    float* out = (float*)d_out;

    static bool attr_set = false;
    if (!attr_set) {
        cudaFuncSetAttribute(quanv_v2k_kernel,
                             cudaFuncAttributeMaxDynamicSharedMemorySize, SMEM_BYTES);
        attr_set = true;
    }
    quanv_v2k_kernel<<<148, NTHREADS, SMEM_BYTES>>>(x, w, out);
}

// round 17
// speedup vs baseline: 1.7971x; 1.1444x over previous
#include <cuda_runtime.h>
#include <cuda_fp16.h>
#include <cstdint>

// ---------------- Problem constants ----------------
#define BATCH   16
#define CIN     32
#define WH_IN   224
#define WH_OUT  222
#define COUT    64
#define KSTEPS  18
#define TILES_PER_CTA 48                 // 148 CTAs * 48 = 7104 = 16*222*2
#define OPLANE  (BATCH * WH_OUT * WH_OUT)
#define NTHREADS 384

// ---------------- SMEM layout ----------------
// A: ring of 6 y-row slots, each [16 chan-pairs][AST u32 cols] fp16x2.
// AST = 136: 136 % 32 == 8 -> A LDS banks 8q+r conflict-free; %4==0 -> STS.128 ok.
#define AST        136
#define SLOT_BYTES (16 * AST * 4)        // 8704
#define NSLOTS     6
#define A_BYTES    (NSLOTS * SLOT_BYTES) // 52224
#define SM_B       A_BYTES
// B row: 72 v2-slots (8B); stride 672B -> 168 words == 8 (mod 32):
// per 16-lane LDS.64 phase, words r*8 + 2q + {0,1} = 0..31 all distinct.
#define BSTR       672
#define SMEM_BYTES (SM_B + COUT * BSTR)  // 95232

// Barrier ids: full[it&3] = 1..4 (256), empty[it&3] = 5..8 (256), rendezvous = 9 (384)
#define BAR_SYNC(id, n)   asm volatile("bar.sync %0, %1;"   :: "r"(id), "r"(n) : "memory")
#define BAR_ARRIVE(id, n) asm volatile("bar.arrive %0, %1;" :: "r"(id), "r"(n) : "memory")
#define MEMBAR_CTA()      asm volatile("membar.cta;" ::: "memory")

// ---------------- helpers ----------------
static __device__ __forceinline__ uint32_t smem_u32(const void* p) {
    uint32_t a;
    asm("{ .reg .u64 t; cvta.to.shared.u64 t, %1; cvt.u32.u64 %0, t; }" : "=r"(a) : "l"(p));
    return a;
}
static __device__ __forceinline__ uint32_t lds_u32(uint32_t a) {
    uint32_t v; asm volatile("ld.shared.b32 %0, [%1];" : "=r"(v) : "r"(a)); return v;
}
static __device__ __forceinline__ void lds_u64(uint32_t a, uint32_t* v) {
    asm volatile("ld.shared.v2.b32 {%0,%1}, [%2];" : "=r"(v[0]), "=r"(v[1]) : "r"(a));
}
static __device__ __forceinline__ void sts_u64(uint32_t a, const uint32_t* v) {
    asm volatile("st.shared.v2.b32 [%0], {%1,%2};" :: "r"(a), "r"(v[0]), "r"(v[1]));
}
static __device__ __forceinline__ void sts_u128(uint32_t a, const uint32_t* v) {
    asm volatile("st.shared.v4.b32 [%0], {%1,%2,%3,%4};"
                 :: "r"(a), "r"(v[0]), "r"(v[1]), "r"(v[2]), "r"(v[3]));
}
// pack two f32 -> f16x2 word: LOW half = v0, HIGH half = v1
static __device__ __forceinline__ uint32_t pack_f16x2(float v0, float v1) {
    uint32_t w;
    asm("cvt.rn.f16x2.f32 %0, %1, %2;" : "=r"(w) : "f"(v1), "f"(v0));
    return w;
}
static __device__ __forceinline__ void mma_f16(float* d, const uint32_t* a,
                                               uint32_t b0, uint32_t b1) {
    asm volatile(
        "mma.sync.aligned.m16n8k16.row.col.f32.f16.f16.f32 "
        "{%0,%1,%2,%3}, {%4,%5,%6,%7}, {%8,%9}, {%0,%1,%2,%3};"
        : "+f"(d[0]), "+f"(d[1]), "+f"(d[2]), "+f"(d[3])
        : "r"(a[0]), "r"(a[1]), "r"(a[2]), "r"(a[3]), "r"(b0), "r"(b1));
}
static __device__ __forceinline__ void stg_cs(float* p, float v) {
    asm volatile("st.global.cs.f32 [%0], %1;" :: "l"(p), "f"(v) : "memory");
}

// Stage one input row (16 chan-pairs x 132 cols) into its ring slot.
// All global loads issued first (MLP ~10), then convert + STS.
static __device__ __forceinline__ void stage_row(const float* __restrict__ x,
                                                 int b, int xs, int yr,
                                                 uint32_t a_sm, int ptid) {
    const uint32_t slot = a_sm + (uint32_t)((yr % NSLOTS) * SLOT_BYTES);
    float4 f0[5], f1[5];
    #pragma unroll
    for (int i = 0; i < 5; ++i) {
        const int u = ptid + i * 128;
        if (u < 528) {
            const int c2 = u / 33;
            const int q4 = u - c2 * 33;
            const float* gp = x + ((size_t)(b * CIN + 2 * c2) * WH_IN + yr) * WH_IN
                                + xs + q4 * 4;
            f0[i] = *(const float4*)gp;
            f1[i] = *(const float4*)(gp + WH_IN * WH_IN);
        }
    }
    #pragma unroll
    for (int i = 0; i < 5; ++i) {
        const int u = ptid + i * 128;
        if (u < 528) {
            const int c2 = u / 33;
            const int q4 = u - c2 * 33;
            uint32_t hv[4];
            hv[0] = pack_f16x2(f0[i].x, f1[i].x);
            hv[1] = pack_f16x2(f0[i].y, f1[i].y);
            hv[2] = pack_f16x2(f0[i].z, f1[i].z);
            hv[3] = pack_f16x2(f0[i].w, f1[i].w);
            sts_u128(slot + (uint32_t)((c2 * AST + q4 * 4) * 4), hv);
        }
    }
}

__global__ void __launch_bounds__(NTHREADS, 1)
quanv_fin_kernel(const float* __restrict__ x, const float* __restrict__ w,
                 float* __restrict__ out)
{
    extern __shared__ char smem[];
    const uint32_t sbase = smem_u32(smem);
    const uint32_t a_sm  = sbase;
    const uint32_t b_sm  = sbase + SM_B;

    const int tid = threadIdx.x;
    const int wid = tid >> 5;
    const int lid = tid & 31;
    const int t0  = blockIdx.x * TILES_PER_CTA;

    // ---- one-time: build B = fp16(w), v2 slots {bh(h0), bh(h1)} ----
    #pragma unroll 1
    for (int u = tid; u < COUT * 72; u += NTHREADS) {
        const int n   = u / 72;
        const int rem = u - n * 72;
        const int ks  = rem >> 2;
        const int qq  = rem & 3;
        const int tap = ks % 9, ch = ks / 9;
        uint32_t bw[2];
        #pragma unroll
        for (int h = 0; h < 2; ++h) {
            const int c = 2 * (ch * 8 + qq + 4 * h);
            bw[h] = pack_f16x2(w[n * 288 + c * 9 + tap], w[n * 288 + (c + 1) * 9 + tap]);
        }
        sts_u64(b_sm + (uint32_t)(n * BSTR + rem * 8), bw);
    }
    __syncthreads();

    if (wid < 8) {
        // ======= CONSUMERS: 2 teams x 4 warps; warp = M32 x N64 =======
        const int team = wid >> 2;
        const int wx   = wid & 3;
        const int r = lid >> 2, q = lid & 3;
        const uint32_t bb = b_sm + (uint32_t)(r * BSTR + q * 8);

        uint32_t ab[2][2];
        #pragma unroll
        for (int j = 0; j < 2; ++j)
            #pragma unroll
            for (int h = 0; h < 2; ++h)
                ab[j][h] = a_sm + (uint32_t)(q * AST + wx * 32 + j * 16 + r + 8 * h) * 4;

        #pragma unroll 1
        for (int it = team; it < TILES_PER_CTA; it += 2) {
            const int t    = t0 + it;
            const int g    = t / WH_OUT;
            const int y    = t - g * WH_OUT;
            const int b    = g >> 1;
            const int half = g & 1;
            const int x0   = half ? 94 : 0;
            const int xoff = half ? 2 : 0;

            if ((y == 0 && it > 0) || (y == 1 && it > 1))
                BAR_SYNC(9, 384);                 // boundary rendezvous
            BAR_SYNC(1 + (it & 3), 256);          // rows staged for tile it

            uint32_t sl[3];
            #pragma unroll
            for (int d = 0; d < 3; ++d)
                sl[d] = (uint32_t)(((y + d) % NSLOTS) * SLOT_BYTES) + (uint32_t)(xoff * 4);

            float acc[2][8][4];
            #pragma unroll
            for (int j = 0; j < 2; ++j)
                #pragma unroll
                for (int nb = 0; nb < 8; ++nb)
                    #pragma unroll
                    for (int e = 0; e < 4; ++e) acc[j][nb][e] = 0.0f;

            #pragma unroll
            for (int ks = 0; ks < KSTEPS; ++ks) {
                const int tap = ks % 9, ch = ks / 9;
                const uint32_t off = sl[tap / 3] + (uint32_t)(ch * 8 * AST * 4 + (tap % 3) * 4);
                uint32_t ahi[2][4];
                #pragma unroll
                for (int j = 0; j < 2; ++j) {
                    ahi[j][0] = lds_u32(ab[j][0] + off);
                    ahi[j][1] = lds_u32(ab[j][1] + off);
                    ahi[j][2] = lds_u32(ab[j][0] + off + 4 * AST * 4);
                    ahi[j][3] = lds_u32(ab[j][1] + off + 4 * AST * 4);
                }
                #pragma unroll
                for (int nb = 0; nb < 8; ++nb) {
                    uint32_t bq[2];
                    lds_u64(bb + (uint32_t)(nb * 8 * BSTR + ks * 32), bq);
                    #pragma unroll
                    for (int j = 0; j < 2; ++j)
                        mma_f16(acc[j][nb], ahi[j], bq[0], bq[1]);   // x * fp16(W)
                }
            }

            BAR_ARRIVE(5 + (it & 3), 256);        // smem reads done (ring class)

            float* ob = out + ((size_t)b * WH_OUT + y) * WH_OUT
                            + (size_t)(2 * q) * OPLANE;
            #pragma unroll
            for (int j = 0; j < 2; ++j)
                #pragma unroll
                for (int h = 0; h < 2; ++h) {
                    const int px = x0 + wx * 32 + j * 16 + r + 8 * h;
                    float* p0 = ob + px;
                    #pragma unroll
                    for (int nb = 0; nb < 8; ++nb) {
                        stg_cs(p0 + (size_t)(nb * 8) * OPLANE,       acc[j][nb][2 * h]);
                        stg_cs(p0 + (size_t)(nb * 8 + 1) * OPLANE,   acc[j][nb][2 * h + 1]);
                    }
                }
        }
    } else {
        // ======= PRODUCERS: 4 warps, rolling 1-row stage, 4-deep lead =======
        const int ptid = tid - 256;
        #pragma unroll 1
        for (int it = 0; it < TILES_PER_CTA; ++it) {
            const int t  = t0 + it;
            const int g  = t / WH_OUT;
            const int y  = t - g * WH_OUT;
            const int b  = g >> 1;
            const int xs = (g & 1) ? 92 : 0;

            if (y == 0 && it > 0) BAR_SYNC(9, 384);       // boundary rendezvous
            if (it >= 4) BAR_SYNC(5 + (it & 3), 256);     // ring slot free (tile it-4 done)

            if (it == 0 || y == 0) {
                stage_row(x, b, xs, y + 0, a_sm, ptid);
                stage_row(x, b, xs, y + 1, a_sm, ptid);
                stage_row(x, b, xs, y + 2, a_sm, ptid);
            } else {
                stage_row(x, b, xs, y + 2, a_sm, ptid);
            }
            MEMBAR_CTA();
            BAR_ARRIVE(1 + (it & 3), 256);                // rows staged for tile it
        }
    }
}

extern "C" void kernel_launch(void* const* d_in, const int* in_sizes, int n_in,
                              void* d_out, int out_size)
{
    const float* x = (const float*)d_in[0];
    const float* w = (const float*)d_in[1];
    float* out = (float*)d_out;

    static bool attr_set = false;
    if (!attr_set) {
        cudaFuncSetAttribute(quanv_fin_kernel,
                             cudaFuncAttributeMaxDynamicSharedMemorySize, SMEM_BYTES);
        attr_set = true;
    }
    quanv_fin_kernel<<<148, NTHREADS, SMEM_BYTES>>>(x, w, out);
}